// round 1
// baseline (speedup 1.0000x reference)
#include <cuda_runtime.h>

#define NB 32
#define NC 8
#define NL 2048
#define NK 512
#define NS 64
#define NW (NL - NS + 1)   // 1985

#define BW 64
#define BK 64
#define WTILES_PER_BLOCK 8

// scratch (allocation-free rule: __device__ globals)
__device__ float g_snt[NC * NS * NK];      // normalized shapelets, [c][s][k]
__device__ float g_inv[NB * NC * NW];      // 1 / max(||window||, 1e-8)

// ---------------- Kernel 1: normalize + transpose shapelets ----------------
__global__ void norm_shapelets_kernel(const float* __restrict__ sh) {
    int gw   = (blockIdx.x * blockDim.x + threadIdx.x) >> 5;  // one warp per (c,k)
    int lane = threadIdx.x & 31;
    if (gw >= NC * NK) return;
    int c = gw / NK, k = gw % NK;
    const float* row = sh + (size_t)(c * NK + k) * NS;
    float v0 = row[lane];
    float v1 = row[lane + 32];
    float ss = v0 * v0 + v1 * v1;
    #pragma unroll
    for (int o = 16; o > 0; o >>= 1) ss += __shfl_xor_sync(0xffffffffu, ss, o);
    float inv = 1.0f / fmaxf(sqrtf(ss), 1e-8f);
    g_snt[(c * NS + lane) * NK + k]        = v0 * inv;
    g_snt[(c * NS + lane + 32) * NK + k]   = v1 * inv;
}

// ---------------- Kernel 2: sliding-window inverse norms -------------------
__global__ void window_norms_kernel(const float* __restrict__ x) {
    __shared__ float xs[NL];
    int bc = blockIdx.x;                      // b*NC + c
    const float* row = x + (size_t)bc * NL;
    for (int i = threadIdx.x; i < NL; i += blockDim.x) xs[i] = row[i];
    __syncthreads();
    for (int w = threadIdx.x; w < NW; w += blockDim.x) {
        float ss = 0.f;
        #pragma unroll 16
        for (int s = 0; s < NS; ++s) {
            float v = xs[w + s];
            ss += v * v;
        }
        g_inv[(size_t)bc * NW + w] = 1.0f / fmaxf(sqrtf(ss), 1e-8f);
    }
}

// ---------------- Kernel 3: main GEMM + relu + max --------------------------
// grid: (4 wchunks, NK/BK = 8 ktiles, NB = 32 batches), 256 threads.
// Each block handles 8 w-tiles of 64 w's; 4x4 register micro-tile per thread.
__global__ __launch_bounds__(256, 3)
void maxcos_main_kernel(const float* __restrict__ x, float* __restrict__ out) {
    __shared__ float snt_s[NS][BK];     // 16 KB, reused as reduce buffer
    __shared__ float xs[BW + NS];       // 128 floats
    __shared__ float invs[BW];          // 64 floats

    const int tid = threadIdx.x;
    const int tx  = tid & 15;           // k group
    const int ty  = tid >> 4;           // w group
    const int b   = blockIdx.z;
    const int k0  = blockIdx.y * BK;

    float bmax = 0.f;                   // running max (valid for tid < 64)

    for (int it = 0; it < WTILES_PER_BLOCK; ++it) {
        const int w0 = (blockIdx.x * WTILES_PER_BLOCK + it) * BW;

        float acc[4][4] = {};

        for (int c = 0; c < NC; ++c) {
            __syncthreads();   // protect smem from previous use
            // stage x slice, window inv-norms, shapelet tile
            if (tid < BW + NS) {
                int j = w0 + tid;
                xs[tid] = (j < NL) ? x[((size_t)(b * NC + c)) * NL + j] : 0.f;
            } else if (tid < BW + NS + BW) {
                int wl = tid - (BW + NS);
                int w  = w0 + wl;
                invs[wl] = (w < NW) ? g_inv[((size_t)(b * NC + c)) * NW + w] : 0.f;
            }
            for (int i = tid; i < NS * BK; i += 256) {
                int s  = i >> 6;
                int kk = i & 63;
                snt_s[s][kk] = g_snt[(c * NS + s) * NK + k0 + kk];
            }
            __syncthreads();

            float part[4][4] = {};
            #pragma unroll 8
            for (int s = 0; s < NS; ++s) {
                float xv0 = xs[ty * 4 + 0 + s];
                float xv1 = xs[ty * 4 + 1 + s];
                float xv2 = xs[ty * 4 + 2 + s];
                float xv3 = xs[ty * 4 + 3 + s];
                float4 sv = *reinterpret_cast<const float4*>(&snt_s[s][tx * 4]);
                part[0][0] += xv0 * sv.x; part[0][1] += xv0 * sv.y;
                part[0][2] += xv0 * sv.z; part[0][3] += xv0 * sv.w;
                part[1][0] += xv1 * sv.x; part[1][1] += xv1 * sv.y;
                part[1][2] += xv1 * sv.z; part[1][3] += xv1 * sv.w;
                part[2][0] += xv2 * sv.x; part[2][1] += xv2 * sv.y;
                part[2][2] += xv2 * sv.z; part[2][3] += xv2 * sv.w;
                part[3][0] += xv3 * sv.x; part[3][1] += xv3 * sv.y;
                part[3][2] += xv3 * sv.z; part[3][3] += xv3 * sv.w;
            }
            #pragma unroll
            for (int i = 0; i < 4; ++i) {
                float iv = invs[ty * 4 + i];
                #pragma unroll
                for (int j = 0; j < 4; ++j) acc[i][j] += iv * part[i][j];
            }
        }

        // relu + max over this tile's 4 local w's (init 0 == relu fused)
        float m[4];
        #pragma unroll
        for (int j = 0; j < 4; ++j) {
            float v = 0.f;
            #pragma unroll
            for (int i = 0; i < 4; ++i) v = fmaxf(v, acc[i][j] * 0.125f);
            m[j] = v;
        }

        // cross-ty reduce via smem (reuse snt_s)
        __syncthreads();
        float* red = &snt_s[0][0];
        #pragma unroll
        for (int j = 0; j < 4; ++j) red[ty * 64 + tx * 4 + j] = m[j];
        __syncthreads();
        if (tid < 64) {
            float v = bmax;
            #pragma unroll
            for (int r = 0; r < 16; ++r) v = fmaxf(v, red[r * 64 + tid]);
            bmax = v;
        }
    }

    if (tid < 64) {
        // all candidates >= 0, so int compare == float compare
        atomicMax(reinterpret_cast<int*>(&out[(size_t)b * NK + k0 + tid]),
                  __float_as_int(bmax));
    }
}

// ---------------- launch -----------------------------------------------------
extern "C" void kernel_launch(void* const* d_in, const int* in_sizes, int n_in,
                              void* d_out, int out_size) {
    const float* x  = (const float*)d_in[0];   // (B, C, L)
    const float* sh = (const float*)d_in[1];   // (C, K, S)
    float* out = (float*)d_out;                // (B, 1, K)

    cudaMemsetAsync(out, 0, (size_t)out_size * sizeof(float), 0);

    // 1) normalize shapelets (transposed store)
    {
        int warps = NC * NK;               // 4096
        int threads = 256;                 // 8 warps/block
        int blocks = (warps * 32 + threads - 1) / threads;  // 512
        norm_shapelets_kernel<<<blocks, threads>>>(sh);
    }
    // 2) window inverse norms
    window_norms_kernel<<<NB * NC, 256>>>(x);

    // 3) main fused GEMM + relu + max
    dim3 grid(4, NK / BK, NB);             // (wchunk, ktile, b)
    maxcos_main_kernel<<<grid, 256>>>(x, out);
}

// round 3
// speedup vs baseline: 2.7228x; 2.7228x over previous
#include <cuda_runtime.h>
#include <cuda_bf16.h>
#include <stdint.h>

#define NB 32
#define NC 8
#define NL 2048
#define NK 512
#define NS 64
#define NW (NL - NS + 1)   // 1985
#define MPAD 2048
#define KTOT 512           // NC * NS

// ---------------- device scratch (static, allocation-free) ----------------
__device__ __nv_bfloat16 g_Ahi[(size_t)NB * MPAD * KTOT];  // 64 MB
__device__ __nv_bfloat16 g_Alo[(size_t)NB * MPAD * KTOT];  // 64 MB
__device__ __nv_bfloat16 g_Bhi[(size_t)NK * KTOT];
__device__ __nv_bfloat16 g_Blo[(size_t)NK * KTOT];
__device__ float         g_inv[(size_t)NB * NC * NW];

// ---------------- helpers ----------------
__device__ __forceinline__ uint32_t smem_u32(const void* p) {
    uint32_t a;
    asm("{ .reg .u64 t; cvta.to.shared.u64 t, %1; cvt.u32.u64 %0, t; }"
        : "=r"(a) : "l"(p));
    return a;
}

__device__ __forceinline__ void cp16(uint32_t dst, const void* src) {
    asm volatile("cp.async.cg.shared.global [%0], [%1], 16;" :: "r"(dst), "l"(src));
}

__device__ __forceinline__ void ldsm4(uint32_t* r, uint32_t addr) {
    asm volatile("ldmatrix.sync.aligned.m8n8.x4.shared.b16 {%0,%1,%2,%3}, [%4];"
                 : "=r"(r[0]), "=r"(r[1]), "=r"(r[2]), "=r"(r[3]) : "r"(addr));
}

__device__ __forceinline__ void mma16816(float* d, const uint32_t* a, const uint32_t* b) {
    asm volatile(
        "mma.sync.aligned.m16n8k16.row.col.f32.bf16.bf16.f32 "
        "{%0,%1,%2,%3}, {%4,%5,%6,%7}, {%8,%9}, {%0,%1,%2,%3};"
        : "+f"(d[0]), "+f"(d[1]), "+f"(d[2]), "+f"(d[3])
        : "r"(a[0]), "r"(a[1]), "r"(a[2]), "r"(a[3]), "r"(b[0]), "r"(b[1]));
}

// ---------------- Kernel 1: B = hi/lo bf16 of sn_norm / 8, [k][c*64+s] -----
__global__ void prep_B_kernel(const float* __restrict__ sh) {
    int gw   = (blockIdx.x * blockDim.x + threadIdx.x) >> 5;
    int lane = threadIdx.x & 31;
    if (gw >= NC * NK) return;
    int c = gw / NK, k = gw % NK;
    const float* row = sh + (size_t)(c * NK + k) * NS;
    float v0 = row[lane], v1 = row[lane + 32];
    float ss = v0 * v0 + v1 * v1;
    #pragma unroll
    for (int o = 16; o > 0; o >>= 1) ss += __shfl_xor_sync(0xffffffffu, ss, o);
    float sc = 0.125f / fmaxf(sqrtf(ss), 1e-8f);
    float a0 = v0 * sc, a1 = v1 * sc;
    __nv_bfloat16 h0 = __float2bfloat16(a0);
    __nv_bfloat16 h1 = __float2bfloat16(a1);
    size_t base = (size_t)k * KTOT + c * 64 + lane;
    g_Bhi[base]      = h0;
    g_Bhi[base + 32] = h1;
    g_Blo[base]      = __float2bfloat16(a0 - __bfloat162float(h0));
    g_Blo[base + 32] = __float2bfloat16(a1 - __bfloat162float(h1));
}

// ---------------- Kernel 2: sliding-window inverse norms -------------------
__global__ void window_norms_kernel(const float* __restrict__ x) {
    __shared__ float xs[NL];
    int bc = blockIdx.x;
    const float* row = x + (size_t)bc * NL;
    for (int i = threadIdx.x; i < NL; i += blockDim.x) xs[i] = row[i];
    __syncthreads();
    for (int w = threadIdx.x; w < NW; w += blockDim.x) {
        float ss = 0.f;
        #pragma unroll 16
        for (int s = 0; s < NS; ++s) { float v = xs[w + s]; ss += v * v; }
        g_inv[(size_t)bc * NW + w] = 1.0f / fmaxf(sqrtf(ss), 1e-8f);
    }
}

// ---------------- Kernel 3: im2col A = hi/lo bf16 of x_window * inv --------
__global__ void im2col_kernel(const float* __restrict__ x) {
    __shared__ float xs[192];
    int b = blockIdx.y, w0 = blockIdx.x * 128;
    int tid = threadIdx.x, wid = tid >> 5, lane = tid & 31;
    for (int c = 0; c < NC; ++c) {
        __syncthreads();
        if (tid < 192) {
            int j = w0 + tid;
            xs[tid] = (j < NL) ? x[((size_t)(b * NC + c)) * NL + j] : 0.f;
        }
        __syncthreads();
        #pragma unroll 4
        for (int it = 0; it < 16; ++it) {
            int r = it * 8 + wid;
            int w = w0 + r;
            float inv = (w < NW) ? g_inv[((size_t)(b * NC + c)) * NW + w] : 0.f;
            float a0 = xs[r + 2 * lane] * inv;
            float a1 = xs[r + 2 * lane + 1] * inv;
            __nv_bfloat16 h0 = __float2bfloat16(a0);
            __nv_bfloat16 h1 = __float2bfloat16(a1);
            __nv_bfloat16 l0 = __float2bfloat16(a0 - __bfloat162float(h0));
            __nv_bfloat16 l1 = __float2bfloat16(a1 - __bfloat162float(h1));
            size_t base = ((size_t)(b * MPAD + w)) * KTOT + c * 64 + 2 * lane;
            __nv_bfloat162 hh; hh.x = h0; hh.y = h1;
            __nv_bfloat162 ll; ll.x = l0; ll.y = l1;
            *reinterpret_cast<__nv_bfloat162*>(&g_Ahi[base]) = hh;
            *reinterpret_cast<__nv_bfloat162*>(&g_Alo[base]) = ll;
        }
    }
}

// ---------------- Kernel 4: mma.sync bf16x3 GEMM + relu-max epilogue -------
// Block tile M=128 x N=256, 512 threads (16 warps, 4x4), warp tile 32x64.
// K: 8 chunks of 64, double-buffered cp.async. 3-term bf16 compensation.
#define STAGE_BYTES 98304
#define OFF_ALO 16384
#define OFF_BHI 32768
#define OFF_BLO 65536
#define SMEM_BYTES (2 * STAGE_BYTES)

__global__ __launch_bounds__(512, 1) void gemm_kernel(float* __restrict__ out) {
    extern __shared__ char smem[];
    const uint32_t sb = smem_u32(smem);
    const int tid = threadIdx.x;
    const int wid = tid >> 5, lane = tid & 31;
    const int m0 = blockIdx.x * 128, n0 = blockIdx.y * 256, b = blockIdx.z;

    const int wm = wid & 3, wn = wid >> 2;

    // ldmatrix source rows (see fragment layouts)
    const int t8 = lane >> 3, lr = lane & 7;
    const int arow = wm * 32 + (t8 & 1) * 8 + lr;   // + i*16
    const int achk = t8 >> 1;                        // + 2*ks
    const int brow = wn * 64 + (t8 >> 1) * 8 + lr;  // + p*16
    const int bchk = t8 & 1;                         // + 2*ks
    const int arow7 = arow & 7, brow7 = brow & 7;
    const uint32_t aRowB0 = (uint32_t)(arow * 128);
    const uint32_t bRowB0 = (uint32_t)(brow * 128);

    const __nv_bfloat16* Ah0 = g_Ahi + ((size_t)(b * MPAD + m0)) * KTOT;
    const __nv_bfloat16* Al0 = g_Alo + ((size_t)(b * MPAD + m0)) * KTOT;
    const __nv_bfloat16* Bh0 = g_Bhi + (size_t)n0 * KTOT;
    const __nv_bfloat16* Bl0 = g_Blo + (size_t)n0 * KTOT;

    // stage loader: A 128x64, B 256x64, hi+lo, 16B-chunk XOR swizzle
    auto load_stage = [&](int cc, int s) {
        const uint32_t base = sb + s * STAGE_BYTES;
        const __nv_bfloat16* gah = Ah0 + cc * 64;
        const __nv_bfloat16* gal = Al0 + cc * 64;
        const __nv_bfloat16* gbh = Bh0 + cc * 64;
        const __nv_bfloat16* gbl = Bl0 + cc * 64;
        #pragma unroll
        for (int j = 0; j < 2; ++j) {
            int i = j * 512 + tid;
            int row = i >> 3, c16 = i & 7;
            uint32_t so = (uint32_t)(row * 128 + ((c16 ^ (row & 7)) << 4));
            cp16(base + so, gah + (size_t)row * KTOT + c16 * 8);
            cp16(base + OFF_ALO + so, gal + (size_t)row * KTOT + c16 * 8);
        }
        #pragma unroll
        for (int j = 0; j < 4; ++j) {
            int i = j * 512 + tid;
            int row = i >> 3, c16 = i & 7;
            uint32_t so = (uint32_t)(row * 128 + ((c16 ^ (row & 7)) << 4));
            cp16(base + OFF_BHI + so, gbh + (size_t)row * KTOT + c16 * 8);
            cp16(base + OFF_BLO + so, gbl + (size_t)row * KTOT + c16 * 8);
        }
        asm volatile("cp.async.commit_group;");
    };

    float acc[2][8][4];
    #pragma unroll
    for (int i = 0; i < 2; ++i)
        #pragma unroll
        for (int j = 0; j < 8; ++j)
            #pragma unroll
            for (int c = 0; c < 4; ++c) acc[i][j][c] = 0.f;

    load_stage(0, 0);

    for (int cc = 0; cc < 8; ++cc) {
        if (cc < 7) load_stage(cc + 1, (cc + 1) & 1);
        if (cc < 7) asm volatile("cp.async.wait_group 1;");
        else        asm volatile("cp.async.wait_group 0;");
        __syncthreads();

        const uint32_t base = sb + (cc & 1) * STAGE_BYTES;
        const uint32_t aH = base, aL = base + OFF_ALO;
        const uint32_t bH = base + OFF_BHI, bL = base + OFF_BLO;

        #pragma unroll
        for (int ks = 0; ks < 4; ++ks) {
            uint32_t ah[2][4], al[2][4];
            const uint32_t axo = (uint32_t)(((achk + 2 * ks) ^ arow7) << 4);
            #pragma unroll
            for (int i = 0; i < 2; ++i) {
                ldsm4(ah[i], aH + aRowB0 + (uint32_t)(i * 16 * 128) + axo);
                ldsm4(al[i], aL + aRowB0 + (uint32_t)(i * 16 * 128) + axo);
            }
            const uint32_t bxo = (uint32_t)(((bchk + 2 * ks) ^ brow7) << 4);
            uint32_t bh[4][4];
            #pragma unroll
            for (int p = 0; p < 4; ++p)
                ldsm4(bh[p], bH + bRowB0 + (uint32_t)(p * 16 * 128) + bxo);
            #pragma unroll
            for (int p = 0; p < 4; ++p) {
                #pragma unroll
                for (int i = 0; i < 2; ++i) {
                    mma16816(acc[i][2 * p],     ah[i], &bh[p][0]);
                    mma16816(acc[i][2 * p + 1], ah[i], &bh[p][2]);
                    mma16816(acc[i][2 * p],     al[i], &bh[p][0]);
                    mma16816(acc[i][2 * p + 1], al[i], &bh[p][2]);
                }
            }
            uint32_t bl[4][4];
            #pragma unroll
            for (int p = 0; p < 4; ++p)
                ldsm4(bl[p], bL + bRowB0 + (uint32_t)(p * 16 * 128) + bxo);
            #pragma unroll
            for (int p = 0; p < 4; ++p) {
                #pragma unroll
                for (int i = 0; i < 2; ++i) {
                    mma16816(acc[i][2 * p],     ah[i], &bl[p][0]);
                    mma16816(acc[i][2 * p + 1], ah[i], &bl[p][2]);
                }
            }
        }
        __syncthreads();
    }

    // ---------------- epilogue: max over M (relu via 0-init) ---------------
    int* s_max = reinterpret_cast<int*>(smem);
    for (int i = tid; i < 256; i += 512) s_max[i] = 0;
    __syncthreads();

    #pragma unroll
    for (int j = 0; j < 8; ++j) {
        float v0 = fmaxf(fmaxf(acc[0][j][0], acc[0][j][2]),
                         fmaxf(acc[1][j][0], acc[1][j][2]));
        float v1 = fmaxf(fmaxf(acc[0][j][1], acc[0][j][3]),
                         fmaxf(acc[1][j][1], acc[1][j][3]));
        #pragma unroll
        for (int off = 4; off < 32; off <<= 1) {
            v0 = fmaxf(v0, __shfl_xor_sync(0xffffffffu, v0, off));
            v1 = fmaxf(v1, __shfl_xor_sync(0xffffffffu, v1, off));
        }
        if (lane < 4) {
            int col = wn * 64 + j * 8 + lane * 2;
            atomicMax(&s_max[col],     __float_as_int(v0));
            atomicMax(&s_max[col + 1], __float_as_int(v1));
        }
    }
    __syncthreads();

    if (tid < 256) {
        // all stored values compared against 0-init: int max == relu'd float max
        atomicMax(reinterpret_cast<int*>(out + (size_t)b * NK + n0 + tid), s_max[tid]);
    }
}

// ---------------- launch -----------------------------------------------------
extern "C" void kernel_launch(void* const* d_in, const int* in_sizes, int n_in,
                              void* d_out, int out_size) {
    const float* x  = (const float*)d_in[0];   // (B, C, L)
    const float* sh = (const float*)d_in[1];   // (C, K, S)
    float* out = (float*)d_out;                // (B, 1, K)

    cudaMemsetAsync(out, 0, (size_t)out_size * sizeof(float), 0);

    prep_B_kernel<<<512, 256>>>(sh);
    window_norms_kernel<<<NB * NC, 256>>>(x);
    im2col_kernel<<<dim3(16, NB), 256>>>(x);

    cudaFuncSetAttribute(gemm_kernel, cudaFuncAttributeMaxDynamicSharedMemorySize,
                         SMEM_BYTES);
    gemm_kernel<<<dim3(16, 2, 32), 512, SMEM_BYTES>>>(out);
}

// round 4
// speedup vs baseline: 6.5211x; 2.3950x over previous
#include <cuda_runtime.h>
#include <cuda_fp16.h>
#include <stdint.h>

#define NB 32
#define NC 8
#define NL 2048
#define NK 512
#define NS 64
#define NW (NL - NS + 1)   // 1985
#define MPAD 2048
#define KTOT 512           // NC * NS

// ---------------- device scratch (static, allocation-free) ----------------
__device__ __half g_A[(size_t)NB * MPAD * KTOT];   // 64 MB, [b][w][c*64+s]
__device__ __half g_B[(size_t)NK * KTOT];          // 512 KB, [k][c*64+s]
__device__ float  g_inv[(size_t)NB * NC * NW];

// ---------------- helpers ----------------
__device__ __forceinline__ uint32_t smem_u32(const void* p) {
    uint32_t a;
    asm("{ .reg .u64 t; cvta.to.shared.u64 t, %1; cvt.u32.u64 %0, t; }"
        : "=r"(a) : "l"(p));
    return a;
}

__device__ __forceinline__ void cp16(uint32_t dst, const void* src) {
    asm volatile("cp.async.cg.shared.global [%0], [%1], 16;" :: "r"(dst), "l"(src));
}

__device__ __forceinline__ void ldsm4(uint32_t* r, uint32_t addr) {
    asm volatile("ldmatrix.sync.aligned.m8n8.x4.shared.b16 {%0,%1,%2,%3}, [%4];"
                 : "=r"(r[0]), "=r"(r[1]), "=r"(r[2]), "=r"(r[3]) : "r"(addr));
}

__device__ __forceinline__ void mma16816(float* d, const uint32_t* a, const uint32_t* b) {
    asm volatile(
        "mma.sync.aligned.m16n8k16.row.col.f32.f16.f16.f32 "
        "{%0,%1,%2,%3}, {%4,%5,%6,%7}, {%8,%9}, {%0,%1,%2,%3};"
        : "+f"(d[0]), "+f"(d[1]), "+f"(d[2]), "+f"(d[3])
        : "r"(a[0]), "r"(a[1]), "r"(a[2]), "r"(a[3]), "r"(b[0]), "r"(b[1]));
}

// ---------------- Kernel 1: B = fp16 of sn_norm / 8, layout [k][c*64+s] ----
__global__ void prep_B_kernel(const float* __restrict__ sh) {
    int gw   = (blockIdx.x * blockDim.x + threadIdx.x) >> 5;
    int lane = threadIdx.x & 31;
    if (gw >= NC * NK) return;
    int c = gw / NK, k = gw % NK;
    const float* row = sh + (size_t)(c * NK + k) * NS;
    float v0 = row[lane], v1 = row[lane + 32];
    float ss = v0 * v0 + v1 * v1;
    #pragma unroll
    for (int o = 16; o > 0; o >>= 1) ss += __shfl_xor_sync(0xffffffffu, ss, o);
    float sc = 0.125f / fmaxf(sqrtf(ss), 1e-8f);
    size_t base = (size_t)k * KTOT + c * 64 + lane;
    g_B[base]      = __float2half(v0 * sc);
    g_B[base + 32] = __float2half(v1 * sc);
}

// ---------------- Kernel 2: sliding-window inverse norms -------------------
__global__ void window_norms_kernel(const float* __restrict__ x) {
    __shared__ float xs[NL];
    int bc = blockIdx.x;
    const float* row = x + (size_t)bc * NL;
    for (int i = threadIdx.x; i < NL; i += blockDim.x) xs[i] = row[i];
    __syncthreads();
    for (int w = threadIdx.x; w < NW; w += blockDim.x) {
        float ss = 0.f;
        #pragma unroll 16
        for (int s = 0; s < NS; ++s) { float v = xs[w + s]; ss += v * v; }
        g_inv[(size_t)bc * NW + w] = 1.0f / fmaxf(sqrtf(ss), 1e-8f);
    }
}

// ---------------- Kernel 3: im2col A = fp16 of x_window * inv --------------
// 128 w-rows per block; each lane converts 8 consecutive s and stores 16 B.
__global__ void im2col_kernel(const float* __restrict__ x) {
    __shared__ float xs[192];
    int b = blockIdx.y, w0 = blockIdx.x * 128;
    int tid = threadIdx.x, wid = tid >> 5, lane = tid & 31;
    const int wl_base = wid * 4 + (lane >> 3);   // +32 per iteration
    const int s0 = (lane & 7) * 8;
    for (int c = 0; c < NC; ++c) {
        __syncthreads();
        if (tid < 192) {
            int j = w0 + tid;
            xs[tid] = (j < NL) ? x[((size_t)(b * NC + c)) * NL + j] : 0.f;
        }
        __syncthreads();
        #pragma unroll
        for (int it = 0; it < 4; ++it) {
            int r = it * 32 + wl_base;
            int w = w0 + r;
            float inv = (w < NW) ? g_inv[((size_t)(b * NC + c)) * NW + w] : 0.f;
            __half h[8];
            #pragma unroll
            for (int j = 0; j < 8; ++j) h[j] = __float2half(xs[r + s0 + j] * inv);
            size_t base = ((size_t)(b * MPAD + w)) * KTOT + c * 64 + s0;
            *reinterpret_cast<uint4*>(&g_A[base]) = *reinterpret_cast<uint4*>(h);
        }
    }
}

// ---------------- Kernel 4: fp16 mma.sync GEMM + relu-max epilogue ---------
// Block tile M=128 x N=256, 512 threads (16 warps, 4x4), warp tile 32x64.
// K: 8 chunks of 64, double-buffered cp.async.
#define STAGE_BYTES 49152
#define OFF_B 16384
#define SMEM_BYTES (2 * STAGE_BYTES)

__global__ __launch_bounds__(512, 1) void gemm_kernel(float* __restrict__ out) {
    extern __shared__ char smem[];
    const uint32_t sb = smem_u32(smem);
    const int tid = threadIdx.x;
    const int wid = tid >> 5, lane = tid & 31;
    const int m0 = blockIdx.x * 128, n0 = blockIdx.y * 256, b = blockIdx.z;

    const int wm = wid & 3, wn = wid >> 2;

    const int t8 = lane >> 3, lr = lane & 7;
    const int arow = wm * 32 + (t8 & 1) * 8 + lr;   // + i*16
    const int achk = t8 >> 1;                        // + 2*ks
    const int brow = wn * 64 + (t8 >> 1) * 8 + lr;  // + p*16
    const int bchk = t8 & 1;                         // + 2*ks
    const int arow7 = arow & 7, brow7 = brow & 7;
    const uint32_t aRowB0 = (uint32_t)(arow * 128);
    const uint32_t bRowB0 = (uint32_t)(brow * 128);

    const __half* A0 = g_A + ((size_t)(b * MPAD + m0)) * KTOT;
    const __half* B0 = g_B + (size_t)n0 * KTOT;

    // stage loader: A 128x64 (16 KB) + B 256x64 (32 KB), 16B-chunk XOR swizzle
    auto load_stage = [&](int cc, int s) {
        const uint32_t base = sb + s * STAGE_BYTES;
        const __half* ga = A0 + cc * 64;
        const __half* gb = B0 + cc * 64;
        #pragma unroll
        for (int j = 0; j < 2; ++j) {
            int i = j * 512 + tid;
            int row = i >> 3, c16 = i & 7;
            uint32_t so = (uint32_t)(row * 128 + ((c16 ^ (row & 7)) << 4));
            cp16(base + so, ga + (size_t)row * KTOT + c16 * 8);
        }
        #pragma unroll
        for (int j = 0; j < 4; ++j) {
            int i = j * 512 + tid;
            int row = i >> 3, c16 = i & 7;
            uint32_t so = (uint32_t)(row * 128 + ((c16 ^ (row & 7)) << 4));
            cp16(base + OFF_B + so, gb + (size_t)row * KTOT + c16 * 8);
        }
        asm volatile("cp.async.commit_group;");
    };

    float acc[2][8][4];
    #pragma unroll
    for (int i = 0; i < 2; ++i)
        #pragma unroll
        for (int j = 0; j < 8; ++j)
            #pragma unroll
            for (int c = 0; c < 4; ++c) acc[i][j][c] = 0.f;

    load_stage(0, 0);

    for (int cc = 0; cc < 8; ++cc) {
        if (cc < 7) {
            load_stage(cc + 1, (cc + 1) & 1);
            asm volatile("cp.async.wait_group 1;");
        } else {
            asm volatile("cp.async.wait_group 0;");
        }
        __syncthreads();

        const uint32_t base = sb + (cc & 1) * STAGE_BYTES;
        const uint32_t aH = base, bH = base + OFF_B;

        #pragma unroll
        for (int ks = 0; ks < 4; ++ks) {
            uint32_t ah[2][4];
            const uint32_t axo = (uint32_t)(((achk + 2 * ks) ^ arow7) << 4);
            #pragma unroll
            for (int i = 0; i < 2; ++i)
                ldsm4(ah[i], aH + aRowB0 + (uint32_t)(i * 16 * 128) + axo);
            const uint32_t bxo = (uint32_t)(((bchk + 2 * ks) ^ brow7) << 4);
            uint32_t bh[4][4];
            #pragma unroll
            for (int p = 0; p < 4; ++p)
                ldsm4(bh[p], bH + bRowB0 + (uint32_t)(p * 16 * 128) + bxo);
            #pragma unroll
            for (int p = 0; p < 4; ++p) {
                #pragma unroll
                for (int i = 0; i < 2; ++i) {
                    mma16816(acc[i][2 * p],     ah[i], &bh[p][0]);
                    mma16816(acc[i][2 * p + 1], ah[i], &bh[p][2]);
                }
            }
        }
        __syncthreads();
    }

    // ---------------- epilogue: max over M (relu via 0-init) ---------------
    int* s_max = reinterpret_cast<int*>(smem);
    for (int i = tid; i < 256; i += 512) s_max[i] = 0;
    __syncthreads();

    #pragma unroll
    for (int j = 0; j < 8; ++j) {
        float v0 = fmaxf(fmaxf(acc[0][j][0], acc[0][j][2]),
                         fmaxf(acc[1][j][0], acc[1][j][2]));
        float v1 = fmaxf(fmaxf(acc[0][j][1], acc[0][j][3]),
                         fmaxf(acc[1][j][1], acc[1][j][3]));
        #pragma unroll
        for (int off = 4; off < 32; off <<= 1) {
            v0 = fmaxf(v0, __shfl_xor_sync(0xffffffffu, v0, off));
            v1 = fmaxf(v1, __shfl_xor_sync(0xffffffffu, v1, off));
        }
        if (lane < 4) {
            int col = wn * 64 + j * 8 + lane * 2;
            atomicMax(&s_max[col],     __float_as_int(v0));
            atomicMax(&s_max[col + 1], __float_as_int(v1));
        }
    }
    __syncthreads();

    if (tid < 256) {
        // all candidates >= 0 vs 0-init: signed-int max == relu'd float max
        atomicMax(reinterpret_cast<int*>(out + (size_t)b * NK + n0 + tid), s_max[tid]);
    }
}

// ---------------- launch -----------------------------------------------------
extern "C" void kernel_launch(void* const* d_in, const int* in_sizes, int n_in,
                              void* d_out, int out_size) {
    const float* x  = (const float*)d_in[0];   // (B, C, L)
    const float* sh = (const float*)d_in[1];   // (C, K, S)
    float* out = (float*)d_out;                // (B, 1, K)

    cudaMemsetAsync(out, 0, (size_t)out_size * sizeof(float), 0);

    prep_B_kernel<<<512, 256>>>(sh);
    window_norms_kernel<<<NB * NC, 256>>>(x);
    im2col_kernel<<<dim3(16, NB), 256>>>(x);

    cudaFuncSetAttribute(gemm_kernel, cudaFuncAttributeMaxDynamicSharedMemorySize,
                         SMEM_BYTES);
    gemm_kernel<<<dim3(16, 2, 32), 512, SMEM_BYTES>>>(out);
}

// round 5
// speedup vs baseline: 6.8975x; 1.0577x over previous
#include <cuda_runtime.h>
#include <cuda_fp16.h>
#include <stdint.h>

#define NB 32
#define NC 8
#define NL 2048
#define NK 512
#define NS 64
#define NW (NL - NS + 1)   // 1985
#define MPAD 2048
#define KTOT 512           // NC * NS

// ---------------- device scratch (static, allocation-free) ----------------
__device__ __half g_A[(size_t)NB * MPAD * KTOT];   // 64 MB, [b][w][c*64+s]
__device__ __half g_B[(size_t)NK * KTOT];          // 512 KB, [k][c*64+s]

// ---------------- helpers ----------------
__device__ __forceinline__ uint32_t smem_u32(const void* p) {
    uint32_t a;
    asm("{ .reg .u64 t; cvta.to.shared.u64 t, %1; cvt.u32.u64 %0, t; }"
        : "=r"(a) : "l"(p));
    return a;
}

__device__ __forceinline__ void cp16(uint32_t dst, const void* src) {
    asm volatile("cp.async.cg.shared.global [%0], [%1], 16;" :: "r"(dst), "l"(src));
}

__device__ __forceinline__ void ldsm4(uint32_t* r, uint32_t addr) {
    asm volatile("ldmatrix.sync.aligned.m8n8.x4.shared.b16 {%0,%1,%2,%3}, [%4];"
                 : "=r"(r[0]), "=r"(r[1]), "=r"(r[2]), "=r"(r[3]) : "r"(addr));
}

__device__ __forceinline__ void mma16816(float* d, const uint32_t* a, const uint32_t* b) {
    asm volatile(
        "mma.sync.aligned.m16n8k16.row.col.f32.f16.f16.f32 "
        "{%0,%1,%2,%3}, {%4,%5,%6,%7}, {%8,%9}, {%0,%1,%2,%3};"
        : "+f"(d[0]), "+f"(d[1]), "+f"(d[2]), "+f"(d[3])
        : "r"(a[0]), "r"(a[1]), "r"(a[2]), "r"(a[3]), "r"(b[0]), "r"(b[1]));
}

// ---------------- Kernel 1: B = fp16 of sn_norm / 8, layout [k][c*64+s] ----
__global__ void prep_B_kernel(const float* __restrict__ sh) {
    int gw   = (blockIdx.x * blockDim.x + threadIdx.x) >> 5;
    int lane = threadIdx.x & 31;
    if (gw >= NC * NK) return;
    int c = gw / NK, k = gw % NK;
    const float* row = sh + (size_t)(c * NK + k) * NS;
    float v0 = row[lane], v1 = row[lane + 32];
    float ss = v0 * v0 + v1 * v1;
    #pragma unroll
    for (int o = 16; o > 0; o >>= 1) ss += __shfl_xor_sync(0xffffffffu, ss, o);
    float sc = 0.125f / fmaxf(sqrtf(ss), 1e-8f);
    size_t base = (size_t)k * KTOT + c * 64 + lane;
    g_B[base]      = __float2half(v0 * sc);
    g_B[base + 32] = __float2half(v1 * sc);
}

// ---------------- Kernel 2: fused window-norm + im2col ---------------------
// 128 w-rows per block. Per channel: stage x slice, compute inv-norms from
// smem, then emit A = fp16(x_window * inv) with vectorized 16B stores.
__global__ __launch_bounds__(256) void im2col_kernel(const float* __restrict__ x) {
    __shared__ float xs[192];
    __shared__ float invs[128];
    const int b = blockIdx.y, w0 = blockIdx.x * 128;
    const int tid = threadIdx.x;
    for (int c = 0; c < NC; ++c) {
        __syncthreads();
        if (tid < 192) {
            int j = w0 + tid;
            xs[tid] = (j < NL) ? x[((size_t)(b * NC + c)) * NL + j] : 0.f;
        }
        __syncthreads();
        if (tid < 128) {
            int w = w0 + tid;
            if (w < NW) {
                float ss = 0.f;
                #pragma unroll 16
                for (int s = 0; s < NS; ++s) { float v = xs[tid + s]; ss += v * v; }
                invs[tid] = 1.0f / fmaxf(sqrtf(ss), 1e-8f);
            } else {
                invs[tid] = 0.f;
            }
        }
        __syncthreads();
        #pragma unroll
        for (int it = 0; it < 4; ++it) {
            int idx = it * 256 + tid;        // 1024 16B-chunks: 128 rows x 8
            int r = idx >> 3, s0 = (idx & 7) * 8;
            float inv = invs[r];
            __half h[8];
            #pragma unroll
            for (int j = 0; j < 8; ++j) h[j] = __float2half(xs[r + s0 + j] * inv);
            size_t base = ((size_t)(b * MPAD + w0 + r)) * KTOT + c * 64 + s0;
            *reinterpret_cast<uint4*>(&g_A[base]) = *reinterpret_cast<uint4*>(h);
        }
    }
}

// ---------------- Kernel 3: fp16 mma.sync GEMM + relu-max epilogue ---------
// Block tile M=128 x N=256, 256 threads (8 warps, 2x4), warp tile 64x64.
// K: 8 chunks of 64, 3-stage cp.async pipeline, one barrier per chunk.
#define NSTAGE 3
#define STAGE_BYTES 49152
#define OFF_B 16384
#define SMEM_BYTES (NSTAGE * STAGE_BYTES)   // 147456

__global__ __launch_bounds__(256, 1) void gemm_kernel(float* __restrict__ out) {
    extern __shared__ char smem[];
    const uint32_t sb = smem_u32(smem);
    const int tid = threadIdx.x;
    const int wid = tid >> 5, lane = tid & 31;
    const int m0 = blockIdx.x * 128, n0 = blockIdx.y * 256, b = blockIdx.z;

    const int wm = wid & 1, wn = wid >> 1;   // 2 x 4 warp grid

    const int t8 = lane >> 3, lr = lane & 7;
    const int arow = wm * 64 + (t8 & 1) * 8 + lr;   // + i*16, i<4
    const int achk = t8 >> 1;                        // + 2*ks
    const int brow = wn * 64 + (t8 >> 1) * 8 + lr;  // + p*16, p<4
    const int bchk = t8 & 1;                         // + 2*ks
    const int arow7 = arow & 7, brow7 = brow & 7;
    const uint32_t aRowB0 = (uint32_t)(arow * 128);
    const uint32_t bRowB0 = (uint32_t)(brow * 128);

    const __half* A0 = g_A + ((size_t)(b * MPAD + m0)) * KTOT;
    const __half* B0 = g_B + (size_t)n0 * KTOT;

    // stage loader: A 128x64 (16 KB) + B 256x64 (32 KB), 16B-chunk XOR swizzle
    auto load_stage = [&](int cc, int s) {
        const uint32_t base = sb + s * STAGE_BYTES;
        const __half* ga = A0 + cc * 64;
        const __half* gb = B0 + cc * 64;
        #pragma unroll
        for (int j = 0; j < 4; ++j) {        // A: 1024 chunks / 256 thr
            int i = j * 256 + tid;
            int row = i >> 3, c16 = i & 7;
            uint32_t so = (uint32_t)(row * 128 + ((c16 ^ (row & 7)) << 4));
            cp16(base + so, ga + (size_t)row * KTOT + c16 * 8);
        }
        #pragma unroll
        for (int j = 0; j < 8; ++j) {        // B: 2048 chunks / 256 thr
            int i = j * 256 + tid;
            int row = i >> 3, c16 = i & 7;
            uint32_t so = (uint32_t)(row * 128 + ((c16 ^ (row & 7)) << 4));
            cp16(base + OFF_B + so, gb + (size_t)row * KTOT + c16 * 8);
        }
        asm volatile("cp.async.commit_group;");
    };

    float acc[4][8][4];
    #pragma unroll
    for (int i = 0; i < 4; ++i)
        #pragma unroll
        for (int j = 0; j < 8; ++j)
            #pragma unroll
            for (int c = 0; c < 4; ++c) acc[i][j][c] = 0.f;

    load_stage(0, 0);
    load_stage(1, 1);

    for (int cc = 0; cc < 8; ++cc) {
        if (cc < 7) asm volatile("cp.async.wait_group 1;");
        else        asm volatile("cp.async.wait_group 0;");
        __syncthreads();
        if (cc < 6) load_stage(cc + 2, (cc + 2) % NSTAGE);

        const uint32_t base = sb + (cc % NSTAGE) * STAGE_BYTES;
        const uint32_t aH = base, bH = base + OFF_B;

        #pragma unroll
        for (int ks = 0; ks < 4; ++ks) {
            uint32_t ah[4][4];
            const uint32_t axo = (uint32_t)(((achk + 2 * ks) ^ arow7) << 4);
            #pragma unroll
            for (int i = 0; i < 4; ++i)
                ldsm4(ah[i], aH + aRowB0 + (uint32_t)(i * 16 * 128) + axo);
            uint32_t bh[4][4];
            const uint32_t bxo = (uint32_t)(((bchk + 2 * ks) ^ brow7) << 4);
            #pragma unroll
            for (int p = 0; p < 4; ++p)
                ldsm4(bh[p], bH + bRowB0 + (uint32_t)(p * 16 * 128) + bxo);
            #pragma unroll
            for (int p = 0; p < 4; ++p) {
                #pragma unroll
                for (int i = 0; i < 4; ++i) {
                    mma16816(acc[i][2 * p],     ah[i], &bh[p][0]);
                    mma16816(acc[i][2 * p + 1], ah[i], &bh[p][2]);
                }
            }
        }
    }
    __syncthreads();   // protect smem reuse below

    // ---------------- epilogue: max over M (relu via 0-init) ---------------
    int* s_max = reinterpret_cast<int*>(smem);
    if (tid < 256) s_max[tid] = 0;
    __syncthreads();

    #pragma unroll
    for (int j = 0; j < 8; ++j) {
        float v0 = fmaxf(fmaxf(acc[0][j][0], acc[0][j][2]),
                         fmaxf(acc[1][j][0], acc[1][j][2]));
        v0 = fmaxf(v0, fmaxf(fmaxf(acc[2][j][0], acc[2][j][2]),
                             fmaxf(acc[3][j][0], acc[3][j][2])));
        float v1 = fmaxf(fmaxf(acc[0][j][1], acc[0][j][3]),
                         fmaxf(acc[1][j][1], acc[1][j][3]));
        v1 = fmaxf(v1, fmaxf(fmaxf(acc[2][j][1], acc[2][j][3]),
                             fmaxf(acc[3][j][1], acc[3][j][3])));
        #pragma unroll
        for (int off = 4; off < 32; off <<= 1) {
            v0 = fmaxf(v0, __shfl_xor_sync(0xffffffffu, v0, off));
            v1 = fmaxf(v1, __shfl_xor_sync(0xffffffffu, v1, off));
        }
        if (lane < 4) {
            int col = wn * 64 + j * 8 + lane * 2;
            atomicMax(&s_max[col],     __float_as_int(v0));
            atomicMax(&s_max[col + 1], __float_as_int(v1));
        }
    }
    __syncthreads();

    if (tid < 256) {
        // all candidates >= 0 vs 0-init: signed-int max == relu'd float max
        atomicMax(reinterpret_cast<int*>(out + (size_t)b * NK + n0 + tid), s_max[tid]);
    }
}

// ---------------- launch -----------------------------------------------------
extern "C" void kernel_launch(void* const* d_in, const int* in_sizes, int n_in,
                              void* d_out, int out_size) {
    const float* x  = (const float*)d_in[0];   // (B, C, L)
    const float* sh = (const float*)d_in[1];   // (C, K, S)
    float* out = (float*)d_out;                // (B, 1, K)

    cudaMemsetAsync(out, 0, (size_t)out_size * sizeof(float), 0);

    prep_B_kernel<<<512, 256>>>(sh);
    im2col_kernel<<<dim3(16, NB), 256>>>(x);

    cudaFuncSetAttribute(gemm_kernel, cudaFuncAttributeMaxDynamicSharedMemorySize,
                         SMEM_BYTES);
    gemm_kernel<<<dim3(16, 2, 32), 256, SMEM_BYTES>>>(out);
}